// round 6
// baseline (speedup 1.0000x reference)
#include <cuda_runtime.h>

// 2D Haar DWT, single level, on x (8, 512, 512, 32) f32 NHWC.
// Output (8, 256, 256, 128) = concat([ll, lh, hl, hh], channel).
//
// Math (after resolving symmetric pad + [1::2] downsample, borders never hit):
//   a0 = x[2i,2j]+x[2i,2j+1], a1 = x[2i+1,2j]+x[2i+1,2j+1]
//   d0 = x[2i,2j+1]-x[2i,2j], d1 = x[2i+1,2j+1]-x[2i+1,2j]
//   ll = 0.5*(a0+a1), lh = 0.5*(a1-a0), hl = 0.5*(d0+d1), hh = 0.5*(d1-d0)
//
// R3: persistent grid-stride version — 1216 CTAs (152 SMs x 8 resident CTAs)
// = exactly one CTA wave; removes ~13 wave transitions of the flat launch.

#define DWT_N 8
#define DWT_H 512
#define DWT_W 512
#define OUT_H 256
#define OUT_W 256
#define TOTAL_TASKS (8u * 256u * 256u * 8u)   // 4,194,304 float4-tasks

__device__ __forceinline__ float4 f4add(float4 a, float4 b) {
    return make_float4(a.x + b.x, a.y + b.y, a.z + b.z, a.w + b.w);
}
__device__ __forceinline__ float4 f4sub(float4 a, float4 b) {
    return make_float4(a.x - b.x, a.y - b.y, a.z - b.z, a.w - b.w);
}
__device__ __forceinline__ float4 f4half(float4 a) {
    return make_float4(0.5f * a.x, 0.5f * a.y, 0.5f * a.z, 0.5f * a.w);
}

__global__ __launch_bounds__(256)
void haar_dwt_kernel(const float4* __restrict__ xin, float4* __restrict__ out) {
    const unsigned stride = gridDim.x * blockDim.x;
    // g layout: [n (3b)][i (8b)][j (8b)][ch4 (3b)]
    for (unsigned g = blockIdx.x * blockDim.x + threadIdx.x; g < TOTAL_TASKS;
         g += stride) {
        unsigned ch4 = g & 7u;          // float4 index within 32 channels
        unsigned pix = g >> 3;
        unsigned j   = pix & 255u;
        unsigned i   = (pix >> 8) & 255u;
        unsigned n   = pix >> 16;

        // Input float4 index for (n, h, w, c4): ((n*512 + h)*512 + w)*8 + c4
        unsigned row0   = (n * (unsigned)DWT_H + 2u * i) * (unsigned)DWT_W + 2u * j;
        unsigned base00 = row0 * 8u + ch4;

        float4 x00 = xin[base00];
        float4 x01 = xin[base00 + 8u];
        float4 x10 = xin[base00 + (unsigned)DWT_W * 8u];
        float4 x11 = xin[base00 + (unsigned)DWT_W * 8u + 8u];

        float4 a0 = f4add(x00, x01);
        float4 a1 = f4add(x10, x11);
        float4 d0 = f4sub(x01, x00);
        float4 d1 = f4sub(x11, x10);

        float4 ll = f4half(f4add(a0, a1));
        float4 lh = f4half(f4sub(a1, a0));
        float4 hl = f4half(f4add(d0, d1));
        float4 hh = f4half(f4sub(d1, d0));

        // Output float4 index for (n, i, j, oc4): ((n*256+i)*256+j)*32 + oc4
        // (128 channels = 32 float4s; band b occupies oc4 = b*8 + ch4)
        unsigned obase = ((n * (unsigned)OUT_H + i) * (unsigned)OUT_W + j) * 32u + ch4;
        out[obase]       = ll;
        out[obase + 8u]  = lh;
        out[obase + 16u] = hl;
        out[obase + 24u] = hh;
    }
}

extern "C" void kernel_launch(void* const* d_in, const int* in_sizes, int n_in,
                              void* d_out, int out_size) {
    const float4* x = (const float4*)d_in[0];
    float4* out = (float4*)d_out;
    // Persistent single-wave launch: 152 SMs * 8 resident CTAs (256 thr, ~30 regs)
    const int threads = 256;
    const int blocks = 152 * 8;  // 1216
    haar_dwt_kernel<<<blocks, threads>>>(x, out);
}

// round 11
// speedup vs baseline: 1.2256x; 1.2256x over previous
#include <cuda_runtime.h>

// 2D Haar DWT, single level, on x (8, 512, 512, 32) f32 NHWC.
// Output (8, 256, 256, 128) = concat([ll, lh, hl, hh], channel).
//
// Math (after resolving symmetric pad + [1::2] downsample, borders never hit):
//   a0 = x[2i,2j]+x[2i,2j+1], a1 = x[2i+1,2j]+x[2i+1,2j+1]
//   d0 = x[2i,2j+1]-x[2i,2j], d1 = x[2i+1,2j+1]-x[2i+1,2j]
//   ll = 0.5*(a0+a1), lh = 0.5*(a1-a0), hl = 0.5*(d0+d1), hh = 0.5*(d1-d0)
//
// R7: revert to flat launch (R2 structure, measured 75.4us kernel / 80.7% DRAM;
// persistent variant regressed to 86.2us / 71.3% DRAM in R6). Add streaming
// cache hints: __ldcs on loads (read-once) and __stcs on stores (write-once,
// no reuse) to cut L2 read/write stream interference.

#define DWT_N 8
#define DWT_H 512
#define DWT_W 512
#define OUT_H 256
#define OUT_W 256

__device__ __forceinline__ float4 f4add(float4 a, float4 b) {
    return make_float4(a.x + b.x, a.y + b.y, a.z + b.z, a.w + b.w);
}
__device__ __forceinline__ float4 f4sub(float4 a, float4 b) {
    return make_float4(a.x - b.x, a.y - b.y, a.z - b.z, a.w - b.w);
}
__device__ __forceinline__ float4 f4half(float4 a) {
    return make_float4(0.5f * a.x, 0.5f * a.y, 0.5f * a.z, 0.5f * a.w);
}

__global__ __launch_bounds__(256)
void haar_dwt_kernel(const float4* __restrict__ xin, float4* __restrict__ out) {
    // One thread = 4 channels (one float4) of one output pixel.
    // g layout: [n (3b)][i (8b)][j (8b)][ch4 (3b)]  -> 2^22 = 4,194,304 threads
    unsigned g = blockIdx.x * blockDim.x + threadIdx.x;
    unsigned ch4 = g & 7u;          // float4 index within 32 channels
    unsigned pix = g >> 3;
    unsigned j   = pix & 255u;
    unsigned i   = (pix >> 8) & 255u;
    unsigned n   = pix >> 16;

    // Input float4 index for (n, h, w, c4): ((n*512 + h)*512 + w)*8 + c4
    unsigned row0   = (n * (unsigned)DWT_H + 2u * i) * (unsigned)DWT_W + 2u * j;
    unsigned base00 = row0 * 8u + ch4;

    float4 x00 = __ldcs(&xin[base00]);
    float4 x01 = __ldcs(&xin[base00 + 8u]);
    float4 x10 = __ldcs(&xin[base00 + (unsigned)DWT_W * 8u]);
    float4 x11 = __ldcs(&xin[base00 + (unsigned)DWT_W * 8u + 8u]);

    float4 a0 = f4add(x00, x01);
    float4 a1 = f4add(x10, x11);
    float4 d0 = f4sub(x01, x00);
    float4 d1 = f4sub(x11, x10);

    float4 ll = f4half(f4add(a0, a1));
    float4 lh = f4half(f4sub(a1, a0));
    float4 hl = f4half(f4add(d0, d1));
    float4 hh = f4half(f4sub(d1, d0));

    // Output float4 index for (n, i, j, oc4): ((n*256+i)*256+j)*32 + oc4
    // (128 channels = 32 float4s; band b occupies oc4 = b*8 + ch4)
    unsigned obase = ((n * (unsigned)OUT_H + i) * (unsigned)OUT_W + j) * 32u + ch4;
    __stcs(&out[obase],       ll);
    __stcs(&out[obase + 8u],  lh);
    __stcs(&out[obase + 16u], hl);
    __stcs(&out[obase + 24u], hh);
}

extern "C" void kernel_launch(void* const* d_in, const int* in_sizes, int n_in,
                              void* d_out, int out_size) {
    const float4* x = (const float4*)d_in[0];
    float4* out = (float4*)d_out;
    // total threads: 8 * 256 * 256 * 8 = 4,194,304 ; flat launch (no loop)
    const int threads = 256;
    const int blocks = (DWT_N * OUT_H * OUT_W * 8) / threads;  // 16384
    haar_dwt_kernel<<<blocks, threads>>>(x, out);
}